// round 2
// baseline (speedup 1.0000x reference)
#include <cuda_runtime.h>
#include <cstdint>

#define SEQ   4096
#define EMB   1024
#define NH    16
#define HD    64
#define WIN   256
#define QKV_N 3072
#define LDP   68              // smem row stride (floats), keeps float4 alignment
#define ATTN_SMEM (4 * 64 * LDP * 4)

static __device__ float g_qkv[SEQ * QKV_N];   // [s, 3*E]: q | k | v interleaved per reference reshape
static __device__ float g_attn[SEQ * EMB];    // attention context, [s, e]

// ---------------------------------------------------------------------------
// Classic 128x128x8 register-tiled SGEMM: C[M,N] = A[M,K] @ B[K,N], row-major.
// 256 threads, each computes an 8x8 fragment. Dims must be multiples of tile.
// ---------------------------------------------------------------------------
__global__ __launch_bounds__(256) void sgemm128(const float* __restrict__ A,
                                                const float* __restrict__ B,
                                                float* __restrict__ C,
                                                int M, int N, int K) {
    __shared__ float As[8][128];
    __shared__ float Bs[8][128];

    const int t  = threadIdx.x;
    const int tx = t & 15;
    const int ty = t >> 4;
    const int bx = blockIdx.x;
    const int by = blockIdx.y;

    const int aRow = t >> 1;          // 0..127
    const int aCol = (t & 1) * 4;     // 0 or 4
    const int bRow = t >> 5;          // 0..7
    const int bCol = (t & 31) * 4;    // 0..124

    const float* Aptr = A + (size_t)(by * 128 + aRow) * K + aCol;
    const float* Bptr = B + (size_t)bRow * N + bx * 128 + bCol;

    float acc[8][8];
#pragma unroll
    for (int i = 0; i < 8; i++)
#pragma unroll
        for (int j = 0; j < 8; j++) acc[i][j] = 0.0f;

    for (int k0 = 0; k0 < K; k0 += 8) {
        float4 a4 = *(const float4*)(Aptr + k0);
        float4 b4 = *(const float4*)(Bptr + (size_t)k0 * N);

        __syncthreads();   // previous iteration's consumers done
        As[aCol + 0][aRow] = a4.x;
        As[aCol + 1][aRow] = a4.y;
        As[aCol + 2][aRow] = a4.z;
        As[aCol + 3][aRow] = a4.w;
        *(float4*)&Bs[bRow][bCol] = b4;
        __syncthreads();

#pragma unroll
        for (int kk = 0; kk < 8; kk++) {
            float4 a0 = *(const float4*)&As[kk][ty * 8];
            float4 a1 = *(const float4*)&As[kk][ty * 8 + 4];
            float4 b0 = *(const float4*)&Bs[kk][tx * 8];
            float4 b1 = *(const float4*)&Bs[kk][tx * 8 + 4];
            float ar[8] = {a0.x, a0.y, a0.z, a0.w, a1.x, a1.y, a1.z, a1.w};
            float br[8] = {b0.x, b0.y, b0.z, b0.w, b1.x, b1.y, b1.z, b1.w};
#pragma unroll
            for (int i = 0; i < 8; i++)
#pragma unroll
                for (int j = 0; j < 8; j++) acc[i][j] += ar[i] * br[j];
        }
    }

#pragma unroll
    for (int i = 0; i < 8; i++) {
        float* Crow = C + (size_t)(by * 128 + ty * 8 + i) * N + bx * 128 + tx * 8;
        *(float4*)Crow       = make_float4(acc[i][0], acc[i][1], acc[i][2], acc[i][3]);
        *(float4*)(Crow + 4) = make_float4(acc[i][4], acc[i][5], acc[i][6], acc[i][7]);
    }
}

// ---------------------------------------------------------------------------
// Sliding-window attention: one block per (64-query tile, head).
// Streams <=5 key tiles of 64, flash-style online softmax.
// Threads: 256 as 16x16; each thread owns a 4x4 fragment (rows 4*ty.., cols 4*tx..).
// Mask is analytic: key j allowed iff j<=i && j>i-WIN.
// ---------------------------------------------------------------------------
__global__ __launch_bounds__(256) void attn_kernel(const float* __restrict__ qkv,
                                                   float* __restrict__ ctx) {
    extern __shared__ float sm[];
    float* Qs = sm;
    float* Ks = sm + 64 * LDP;
    float* Vs = sm + 2 * 64 * LDP;
    float* Ps = sm + 3 * 64 * LDP;

    const int qb = blockIdx.x;
    const int h  = blockIdx.y;
    const int t  = threadIdx.x;
    const int tx = t & 15;
    const int ty = t >> 4;
    const int q0 = qb * 64;
    const int qcol = h * HD;

    // Load Q tile [64 x 64]
#pragma unroll
    for (int i = 0; i < 4; i++) {
        int idx = t + 256 * i;
        int r = idx >> 4, c4 = (idx & 15) << 2;
        *(float4*)&Qs[r * LDP + c4] =
            *(const float4*)&qkv[(size_t)(q0 + r) * QKV_N + qcol + c4];
    }

    float m[4], l[4], o[4][4];
#pragma unroll
    for (int i = 0; i < 4; i++) {
        m[i] = -1e30f;
        l[i] = 0.0f;
#pragma unroll
        for (int j = 0; j < 4; j++) o[i][j] = 0.0f;
    }

    const int ktlo = (qb - 4 < 0) ? 0 : qb - 4;
    for (int kt = ktlo; kt <= qb; kt++) {
        const int k0 = kt * 64;
        __syncthreads();   // previous tile's smem consumers done (also orders Q for 1st iter)
#pragma unroll
        for (int i = 0; i < 4; i++) {
            int idx = t + 256 * i;
            int r = idx >> 4, c4 = (idx & 15) << 2;
            *(float4*)&Ks[r * LDP + c4] =
                *(const float4*)&qkv[(size_t)(k0 + r) * QKV_N + EMB + qcol + c4];
            *(float4*)&Vs[r * LDP + c4] =
                *(const float4*)&qkv[(size_t)(k0 + r) * QKV_N + 2 * EMB + qcol + c4];
        }
        __syncthreads();

        // S = Q K^T for this thread's 4x4 fragment
        float acc[4][4];
#pragma unroll
        for (int i = 0; i < 4; i++)
#pragma unroll
            for (int j = 0; j < 4; j++) acc[i][j] = 0.0f;

#pragma unroll
        for (int d = 0; d < 64; d += 4) {
            float4 q4[4], k4[4];
#pragma unroll
            for (int i = 0; i < 4; i++) q4[i] = *(const float4*)&Qs[(4 * ty + i) * LDP + d];
#pragma unroll
            for (int j = 0; j < 4; j++) k4[j] = *(const float4*)&Ks[(4 * tx + j) * LDP + d];
#pragma unroll
            for (int i = 0; i < 4; i++)
#pragma unroll
                for (int j = 0; j < 4; j++) {
                    acc[i][j] += q4[i].x * k4[j].x + q4[i].y * k4[j].y +
                                 q4[i].z * k4[j].z + q4[i].w * k4[j].w;
                }
        }

        // masked online softmax per row
#pragma unroll
        for (int i = 0; i < 4; i++) {
            const int qi = q0 + 4 * ty + i;
            float sv[4];
            float mt = -1e30f;
#pragma unroll
            for (int j = 0; j < 4; j++) {
                int kj = k0 + 4 * tx + j;
                bool ok = (kj <= qi) && (kj > qi - WIN);
                sv[j] = ok ? acc[i][j] * 0.125f : -1e30f;
                mt = fmaxf(mt, sv[j]);
            }
#pragma unroll
            for (int off = 8; off; off >>= 1)
                mt = fmaxf(mt, __shfl_xor_sync(0xffffffffu, mt, off, 16));

            float alpha = 1.0f;
            if (mt > m[i]) { alpha = __expf(m[i] - mt); m[i] = mt; }

            float p[4];
            float ls = 0.0f;
#pragma unroll
            for (int j = 0; j < 4; j++) {
                p[j] = (sv[j] > -1e29f) ? __expf(sv[j] - m[i]) : 0.0f;
                ls += p[j];
            }
#pragma unroll
            for (int off = 8; off; off >>= 1)
                ls += __shfl_xor_sync(0xffffffffu, ls, off, 16);

            l[i] = l[i] * alpha + ls;
#pragma unroll
            for (int c = 0; c < 4; c++) o[i][c] *= alpha;

            *(float4*)&Ps[(4 * ty + i) * LDP + 4 * tx] = make_float4(p[0], p[1], p[2], p[3]);
        }
        __syncthreads();

        // O += P V for this thread's rows (4*ty..) and dims (4*tx..)
#pragma unroll
        for (int j = 0; j < 64; j += 4) {
            float4 p4[4];
#pragma unroll
            for (int i = 0; i < 4; i++) p4[i] = *(const float4*)&Ps[(4 * ty + i) * LDP + j];
#pragma unroll
            for (int jj = 0; jj < 4; jj++) {
                float4 vv = *(const float4*)&Vs[(j + jj) * LDP + 4 * tx];
#pragma unroll
                for (int i = 0; i < 4; i++) {
                    float pj = ((const float*)&p4[i])[jj];
                    o[i][0] += pj * vv.x;
                    o[i][1] += pj * vv.y;
                    o[i][2] += pj * vv.z;
                    o[i][3] += pj * vv.w;
                }
            }
        }
    }

    // epilogue: normalize and store to [s, e] layout
#pragma unroll
    for (int i = 0; i < 4; i++) {
        float inv = 1.0f / l[i];
        int row = q0 + 4 * ty + i;
        *(float4*)&g_attn[(size_t)row * EMB + qcol + 4 * tx] =
            make_float4(o[i][0] * inv, o[i][1] * inv, o[i][2] * inv, o[i][3] * inv);
    }
    (void)ctx;
}

// ---------------------------------------------------------------------------
extern "C" void kernel_launch(void* const* d_in, const int* in_sizes, int n_in,
                              void* d_out, int out_size) {
    const float* x     = (const float*)d_in[0];
    // d_in[1] = allowed_mask (bool) — intentionally unused; mask is analytic.
    const float* w_qkv = (const float*)d_in[2];
    const float* w_out = (const float*)d_in[3];
    float* out = (float*)d_out;

    float *qkv, *ctx;
    cudaGetSymbolAddress((void**)&qkv, g_qkv);
    cudaGetSymbolAddress((void**)&ctx, g_attn);

    cudaFuncSetAttribute(attn_kernel, cudaFuncAttributeMaxDynamicSharedMemorySize, ATTN_SMEM);

    // 1) qkv = x @ w_qkv   [4096,1024]@[1024,3072]
    sgemm128<<<dim3(QKV_N / 128, SEQ / 128), 256>>>(x, w_qkv, qkv, SEQ, QKV_N, EMB);
    // 2) attention
    attn_kernel<<<dim3(SEQ / 64, NH), 256, ATTN_SMEM>>>(qkv, ctx);
    // 3) out = ctx @ w_out [4096,1024]@[1024,1024]
    sgemm128<<<dim3(EMB / 128, SEQ / 128), 256>>>(ctx, w_out, out, SEQ, EMB, EMB);
}

// round 3
// speedup vs baseline: 2.2303x; 2.2303x over previous
#include <cuda_runtime.h>
#include <cstdint>

#define SEQ   4096
#define EMB   1024
#define NH    16
#define HD    64
#define WIN   256
#define QKV_N 3072
#define LDP   68
#define ATTN_SMEM (4 * 64 * LDP * 4)

// tf32 GEMM tiling
#define BM 128
#define BN 128
#define BK 32
#define LDA 36            // floats; bank = 4*(lane/4)+(lane%4) -> conflict-free
#define LDB 136           // floats; bank = 8*(lane%4)+(lane/4) -> conflict-free
#define ABUF (BM * LDA)
#define BBUF (BK * LDB)
#define GEMM_SMEM ((2 * ABUF + 2 * BBUF) * 4)

static __device__ float g_qkv[SEQ * QKV_N];
static __device__ float g_attn[SEQ * EMB];

__device__ __forceinline__ uint32_t f2tf(float x) {
    uint32_t r;
    asm("cvt.rna.tf32.f32 %0, %1;" : "=r"(r) : "f"(x));
    return r;
}

__device__ __forceinline__ void mma_tf32(float d[4], const uint32_t a[4], const uint32_t b[2]) {
    asm volatile(
        "mma.sync.aligned.m16n8k8.row.col.f32.tf32.tf32.f32 "
        "{%0,%1,%2,%3}, {%4,%5,%6,%7}, {%8,%9}, {%0,%1,%2,%3};\n"
        : "+f"(d[0]), "+f"(d[1]), "+f"(d[2]), "+f"(d[3])
        : "r"(a[0]), "r"(a[1]), "r"(a[2]), "r"(a[3]), "r"(b[0]), "r"(b[1]));
}

__device__ __forceinline__ void cp16(float* smem_dst, const float* gsrc) {
    uint32_t saddr = (uint32_t)__cvta_generic_to_shared(smem_dst);
    asm volatile("cp.async.cg.shared.global [%0], [%1], 16;\n" :: "r"(saddr), "l"(gsrc) : "memory");
}

// ---------------------------------------------------------------------------
// tf32 tensor-core GEMM: C[M,N] = A[M,K] @ B[K,N], row-major, fp32 accumulate.
// 128x128x32 tile, 256 threads (8 warps as 2x4, warp tile 64x32).
// ---------------------------------------------------------------------------
__global__ __launch_bounds__(256, 2) void tf32gemm(const float* __restrict__ A,
                                                   const float* __restrict__ B,
                                                   float* __restrict__ C,
                                                   int M, int N, int K) {
    extern __shared__ float sm[];
    float* As = sm;                 // [2][BM][LDA]
    float* Bs = sm + 2 * ABUF;      // [2][BK][LDB]

    const int t    = threadIdx.x;
    const int w    = t >> 5;
    const int lane = t & 31;
    const int wm   = w >> 2;        // 0..1
    const int wn   = w & 3;         // 0..3
    const int lr   = lane >> 2;     // 0..7
    const int lc   = lane & 3;      // 0..3
    const int bx   = blockIdx.x;
    const int by   = blockIdx.y;

    // loader mapping: 4 A-chunks + 4 B-chunks of 16B per thread per tile
    const int aRow[1] = {0};  (void)aRow;

    float acc[4][4][4];
#pragma unroll
    for (int i = 0; i < 4; i++)
#pragma unroll
        for (int j = 0; j < 4; j++)
#pragma unroll
            for (int c = 0; c < 4; c++) acc[i][j][c] = 0.0f;

    const int NT = K / BK;

    // prologue: load tile 0 into buf 0
    {
#pragma unroll
        for (int i = 0; i < 4; i++) {
            int id = t + 256 * i;                 // 0..1023
            int r = id >> 3, c4 = (id & 7) << 2;  // A: 128 rows x 8 chunks
            cp16(&As[r * LDA + c4], &A[(size_t)(by * BM + r) * K + c4]);
        }
#pragma unroll
        for (int i = 0; i < 4; i++) {
            int id = t + 256 * i;
            int r = id >> 5, c4 = (id & 31) << 2; // B: 32 rows x 32 chunks
            cp16(&Bs[r * LDB + c4], &B[(size_t)r * N + bx * BN + c4]);
        }
        asm volatile("cp.async.commit_group;\n" ::: "memory");
    }

    for (int kt = 0; kt < NT; kt++) {
        asm volatile("cp.async.wait_group 0;\n" ::: "memory");
        __syncthreads();

        if (kt + 1 < NT) {
            const int k0 = (kt + 1) * BK;
            float* Ad = As + ((kt + 1) & 1) * ABUF;
            float* Bd = Bs + ((kt + 1) & 1) * BBUF;
#pragma unroll
            for (int i = 0; i < 4; i++) {
                int id = t + 256 * i;
                int r = id >> 3, c4 = (id & 7) << 2;
                cp16(&Ad[r * LDA + c4], &A[(size_t)(by * BM + r) * K + k0 + c4]);
            }
#pragma unroll
            for (int i = 0; i < 4; i++) {
                int id = t + 256 * i;
                int r = id >> 5, c4 = (id & 31) << 2;
                cp16(&Bd[r * LDB + c4], &B[(size_t)(k0 + r) * N + bx * BN + c4]);
            }
            asm volatile("cp.async.commit_group;\n" ::: "memory");
        }

        const float* Ab = As + (kt & 1) * ABUF;
        const float* Bb = Bs + (kt & 1) * BBUF;

#pragma unroll
        for (int ks = 0; ks < 4; ks++) {
            uint32_t af[4][4], bf[4][2];
#pragma unroll
            for (int mi = 0; mi < 4; mi++) {
                const float* ap = &Ab[(wm * 64 + mi * 16 + lr) * LDA + ks * 8 + lc];
                af[mi][0] = f2tf(ap[0]);
                af[mi][1] = f2tf(ap[8 * LDA]);
                af[mi][2] = f2tf(ap[4]);
                af[mi][3] = f2tf(ap[8 * LDA + 4]);
            }
#pragma unroll
            for (int ni = 0; ni < 4; ni++) {
                const float* bp = &Bb[(ks * 8 + lc) * LDB + wn * 32 + ni * 8 + lr];
                bf[ni][0] = f2tf(bp[0]);
                bf[ni][1] = f2tf(bp[4 * LDB]);
            }
#pragma unroll
            for (int mi = 0; mi < 4; mi++)
#pragma unroll
                for (int ni = 0; ni < 4; ni++)
                    mma_tf32(acc[mi][ni], af[mi], bf[ni]);
        }
    }

    // epilogue
#pragma unroll
    for (int mi = 0; mi < 4; mi++) {
        const int r0 = by * BM + wm * 64 + mi * 16 + lr;
#pragma unroll
        for (int ni = 0; ni < 4; ni++) {
            const int c0 = bx * BN + wn * 32 + ni * 8 + 2 * lc;
            *(float2*)&C[(size_t)r0 * N + c0]       = make_float2(acc[mi][ni][0], acc[mi][ni][1]);
            *(float2*)&C[(size_t)(r0 + 8) * N + c0] = make_float2(acc[mi][ni][2], acc[mi][ni][3]);
        }
    }
}

// ---------------------------------------------------------------------------
// Sliding-window attention (unchanged from round 1): one block per (64-query
// tile, head), flash-style online softmax, analytic mask.
// ---------------------------------------------------------------------------
__global__ __launch_bounds__(256) void attn_kernel(const float* __restrict__ qkv,
                                                   float* __restrict__ ctx) {
    extern __shared__ float sm[];
    float* Qs = sm;
    float* Ks = sm + 64 * LDP;
    float* Vs = sm + 2 * 64 * LDP;
    float* Ps = sm + 3 * 64 * LDP;

    const int qb = blockIdx.x;
    const int h  = blockIdx.y;
    const int t  = threadIdx.x;
    const int tx = t & 15;
    const int ty = t >> 4;
    const int q0 = qb * 64;
    const int qcol = h * HD;

#pragma unroll
    for (int i = 0; i < 4; i++) {
        int idx = t + 256 * i;
        int r = idx >> 4, c4 = (idx & 15) << 2;
        *(float4*)&Qs[r * LDP + c4] =
            *(const float4*)&qkv[(size_t)(q0 + r) * QKV_N + qcol + c4];
    }

    float m[4], l[4], o[4][4];
#pragma unroll
    for (int i = 0; i < 4; i++) {
        m[i] = -1e30f;
        l[i] = 0.0f;
#pragma unroll
        for (int j = 0; j < 4; j++) o[i][j] = 0.0f;
    }

    const int ktlo = (qb - 4 < 0) ? 0 : qb - 4;
    for (int kt = ktlo; kt <= qb; kt++) {
        const int k0 = kt * 64;
        __syncthreads();
#pragma unroll
        for (int i = 0; i < 4; i++) {
            int idx = t + 256 * i;
            int r = idx >> 4, c4 = (idx & 15) << 2;
            *(float4*)&Ks[r * LDP + c4] =
                *(const float4*)&qkv[(size_t)(k0 + r) * QKV_N + EMB + qcol + c4];
            *(float4*)&Vs[r * LDP + c4] =
                *(const float4*)&qkv[(size_t)(k0 + r) * QKV_N + 2 * EMB + qcol + c4];
        }
        __syncthreads();

        float acc[4][4];
#pragma unroll
        for (int i = 0; i < 4; i++)
#pragma unroll
            for (int j = 0; j < 4; j++) acc[i][j] = 0.0f;

#pragma unroll
        for (int d = 0; d < 64; d += 4) {
            float4 q4[4], k4[4];
#pragma unroll
            for (int i = 0; i < 4; i++) q4[i] = *(const float4*)&Qs[(4 * ty + i) * LDP + d];
#pragma unroll
            for (int j = 0; j < 4; j++) k4[j] = *(const float4*)&Ks[(4 * tx + j) * LDP + d];
#pragma unroll
            for (int i = 0; i < 4; i++)
#pragma unroll
                for (int j = 0; j < 4; j++) {
                    acc[i][j] += q4[i].x * k4[j].x + q4[i].y * k4[j].y +
                                 q4[i].z * k4[j].z + q4[i].w * k4[j].w;
                }
        }

#pragma unroll
        for (int i = 0; i < 4; i++) {
            const int qi = q0 + 4 * ty + i;
            float sv[4];
            float mt = -1e30f;
#pragma unroll
            for (int j = 0; j < 4; j++) {
                int kj = k0 + 4 * tx + j;
                bool ok = (kj <= qi) && (kj > qi - WIN);
                sv[j] = ok ? acc[i][j] * 0.125f : -1e30f;
                mt = fmaxf(mt, sv[j]);
            }
#pragma unroll
            for (int off = 8; off; off >>= 1)
                mt = fmaxf(mt, __shfl_xor_sync(0xffffffffu, mt, off, 16));

            float alpha = 1.0f;
            if (mt > m[i]) { alpha = __expf(m[i] - mt); m[i] = mt; }

            float p[4];
            float ls = 0.0f;
#pragma unroll
            for (int j = 0; j < 4; j++) {
                p[j] = (sv[j] > -1e29f) ? __expf(sv[j] - m[i]) : 0.0f;
                ls += p[j];
            }
#pragma unroll
            for (int off = 8; off; off >>= 1)
                ls += __shfl_xor_sync(0xffffffffu, ls, off, 16);

            l[i] = l[i] * alpha + ls;
#pragma unroll
            for (int c = 0; c < 4; c++) o[i][c] *= alpha;

            *(float4*)&Ps[(4 * ty + i) * LDP + 4 * tx] = make_float4(p[0], p[1], p[2], p[3]);
        }
        __syncthreads();

#pragma unroll
        for (int j = 0; j < 64; j += 4) {
            float4 p4[4];
#pragma unroll
            for (int i = 0; i < 4; i++) p4[i] = *(const float4*)&Ps[(4 * ty + i) * LDP + j];
#pragma unroll
            for (int jj = 0; jj < 4; jj++) {
                float4 vv = *(const float4*)&Vs[(j + jj) * LDP + 4 * tx];
#pragma unroll
                for (int i = 0; i < 4; i++) {
                    float pj = ((const float*)&p4[i])[jj];
                    o[i][0] += pj * vv.x;
                    o[i][1] += pj * vv.y;
                    o[i][2] += pj * vv.z;
                    o[i][3] += pj * vv.w;
                }
            }
        }
    }

#pragma unroll
    for (int i = 0; i < 4; i++) {
        float inv = 1.0f / l[i];
        int row = q0 + 4 * ty + i;
        *(float4*)&g_attn[(size_t)row * EMB + qcol + 4 * tx] =
            make_float4(o[i][0] * inv, o[i][1] * inv, o[i][2] * inv, o[i][3] * inv);
    }
    (void)ctx;
}

// ---------------------------------------------------------------------------
extern "C" void kernel_launch(void* const* d_in, const int* in_sizes, int n_in,
                              void* d_out, int out_size) {
    const float* x     = (const float*)d_in[0];
    const float* w_qkv = (const float*)d_in[2];
    const float* w_out = (const float*)d_in[3];
    float* out = (float*)d_out;

    float *qkv, *ctx;
    cudaGetSymbolAddress((void**)&qkv, g_qkv);
    cudaGetSymbolAddress((void**)&ctx, g_attn);

    static bool attrs_set = false;
    if (!attrs_set) {
        cudaFuncSetAttribute(attn_kernel, cudaFuncAttributeMaxDynamicSharedMemorySize, ATTN_SMEM);
        cudaFuncSetAttribute(tf32gemm, cudaFuncAttributeMaxDynamicSharedMemorySize, GEMM_SMEM);
        attrs_set = true;
    }

    // 1) qkv = x @ w_qkv   [4096,1024]@[1024,3072]
    tf32gemm<<<dim3(QKV_N / BN, SEQ / BM), 256, GEMM_SMEM>>>(x, w_qkv, qkv, SEQ, QKV_N, EMB);
    // 2) attention
    attn_kernel<<<dim3(SEQ / 64, NH), 256, ATTN_SMEM>>>(qkv, ctx);
    // 3) out = ctx @ w_out [4096,1024]@[1024,1024]
    tf32gemm<<<dim3(EMB / BN, SEQ / BM), 256, GEMM_SMEM>>>(ctx, w_out, out, SEQ, EMB, EMB);
}

// round 4
// speedup vs baseline: 3.6874x; 1.6533x over previous
#include <cuda_runtime.h>
#include <cstdint>

#define SEQ   4096
#define EMB   1024
#define NH    16
#define HD    64
#define WIN   256
#define QKV_N 3072

// ---- GEMM tiling ----
#define BM 128
#define BN 128
#define BK 32
#define STG 3
#define LDA 36            // bank = 4*row+col (mod 32) -> conflict-free A-fragment loads
#define LDB 136           // bank = 8*col+row pattern -> conflict-free B-fragment loads
#define ABUF (BM * LDA)
#define BBUF (BK * LDB)
#define GEMM_SMEM ((STG * ABUF + STG * BBUF) * 4)

// ---- attention tiling ----
#define LQ 68             // A/B-row-pattern stride (mod 32 == 4): conflict-free
#define LV 72             // V column-pattern stride (mod 32 == 8): conflict-free
#define ATTN_SMEM ((3 * 64 * LQ + 64 * LV) * 4)

static __device__ float g_qkv[SEQ * QKV_N];    // fp32 q|k|v
static __device__ float g_attn[SEQ * EMB];     // tf32-rounded ctx
static __device__ float g_xr[SEQ * EMB];       // tf32-rounded x
static __device__ float g_wqkvr[EMB * QKV_N];  // tf32-rounded w_qkv
static __device__ float g_woutr[EMB * EMB];    // tf32-rounded w_out

__device__ __forceinline__ uint32_t f2tf(float x) {
    uint32_t r;
    asm("cvt.rna.tf32.f32 %0, %1;" : "=r"(r) : "f"(x));
    return r;
}

__device__ __forceinline__ void mma_tf32(float d[4], const uint32_t a[4], const uint32_t b[2]) {
    asm volatile(
        "mma.sync.aligned.m16n8k8.row.col.f32.tf32.tf32.f32 "
        "{%0,%1,%2,%3}, {%4,%5,%6,%7}, {%8,%9}, {%0,%1,%2,%3};\n"
        : "+f"(d[0]), "+f"(d[1]), "+f"(d[2]), "+f"(d[3])
        : "r"(a[0]), "r"(a[1]), "r"(a[2]), "r"(a[3]), "r"(b[0]), "r"(b[1]));
}

__device__ __forceinline__ void cp16(float* smem_dst, const float* gsrc) {
    uint32_t saddr = (uint32_t)__cvta_generic_to_shared(smem_dst);
    asm volatile("cp.async.cg.shared.global [%0], [%1], 16;\n" :: "r"(saddr), "l"(gsrc) : "memory");
}

// ---------------------------------------------------------------------------
// Elementwise tf32 rounding (rna), vectorized.
// ---------------------------------------------------------------------------
__global__ __launch_bounds__(256) void round_tf32(const float4* __restrict__ src,
                                                  float4* __restrict__ dst, int n4) {
    int i = blockIdx.x * blockDim.x + threadIdx.x;
    if (i < n4) {
        float4 v = src[i];
        v.x = __uint_as_float(f2tf(v.x));
        v.y = __uint_as_float(f2tf(v.y));
        v.z = __uint_as_float(f2tf(v.z));
        v.w = __uint_as_float(f2tf(v.w));
        dst[i] = v;
    }
}

// ---------------------------------------------------------------------------
// tf32 tensor-core GEMM, inputs pre-rounded to tf32. 128x128x32 tile,
// 256 threads (8 warps 2x4, warp tile 64x32), 3-stage cp.async pipeline.
// ---------------------------------------------------------------------------
__global__ __launch_bounds__(256, 2) void tf32gemm(const float* __restrict__ A,
                                                   const float* __restrict__ B,
                                                   float* __restrict__ C,
                                                   int M, int N, int K) {
    extern __shared__ float sm[];
    float* As = sm;                   // [STG][BM][LDA]
    float* Bs = sm + STG * ABUF;      // [STG][BK][LDB]

    const int t    = threadIdx.x;
    const int w    = t >> 5;
    const int lane = t & 31;
    const int wm   = w >> 2;
    const int wn   = w & 3;
    const int lr   = lane >> 2;
    const int lc   = lane & 3;
    const int bx   = blockIdx.x;
    const int by   = blockIdx.y;

    float acc[4][4][4];
#pragma unroll
    for (int i = 0; i < 4; i++)
#pragma unroll
        for (int j = 0; j < 4; j++)
#pragma unroll
            for (int c = 0; c < 4; c++) acc[i][j][c] = 0.0f;

    const int NT = K / BK;

    const int ar = t >> 3, ac4 = (t & 7) << 2;     // A: 128 rows x 8 chunks, 4 rows/thread-step
    const int br = t >> 5, bc4 = (t & 31) << 2;    // B: 32 rows x 32 chunks

#define LOAD_TILE(stage, ktile)                                                        \
    {                                                                                  \
        float* Ad = As + (stage) * ABUF;                                               \
        float* Bd = Bs + (stage) * BBUF;                                               \
        const int k0 = (ktile) * BK;                                                   \
        _Pragma("unroll")                                                              \
        for (int i = 0; i < 4; i++) {                                                  \
            int id = t + 256 * i;                                                      \
            int r = id >> 3, c4 = (id & 7) << 2;                                       \
            cp16(&Ad[r * LDA + c4], &A[(size_t)(by * BM + r) * K + k0 + c4]);          \
        }                                                                              \
        _Pragma("unroll")                                                              \
        for (int i = 0; i < 4; i++) {                                                  \
            int id = t + 256 * i;                                                      \
            int r = id >> 5, c4 = (id & 31) << 2;                                      \
            cp16(&Bd[r * LDB + c4], &B[(size_t)(k0 + r) * N + bx * BN + c4]);          \
        }                                                                              \
    }
    (void)ar; (void)ac4; (void)br; (void)bc4;

    // prologue: stages 0,1
    LOAD_TILE(0, 0);
    asm volatile("cp.async.commit_group;\n" ::: "memory");
    if (NT > 1) LOAD_TILE(1, 1);
    asm volatile("cp.async.commit_group;\n" ::: "memory");

    for (int kt = 0; kt < NT; kt++) {
        asm volatile("cp.async.wait_group 1;\n" ::: "memory");
        __syncthreads();

        if (kt + 2 < NT) LOAD_TILE((kt + 2) % STG, kt + 2);
        asm volatile("cp.async.commit_group;\n" ::: "memory");

        const uint32_t* Ab = (const uint32_t*)(As + (kt % STG) * ABUF);
        const uint32_t* Bb = (const uint32_t*)(Bs + (kt % STG) * BBUF);

#pragma unroll
        for (int ks = 0; ks < 4; ks++) {
            uint32_t af[4][4], bf[4][2];
#pragma unroll
            for (int mi = 0; mi < 4; mi++) {
                const uint32_t* ap = &Ab[(wm * 64 + mi * 16 + lr) * LDA + ks * 8 + lc];
                af[mi][0] = ap[0];
                af[mi][1] = ap[8 * LDA];
                af[mi][2] = ap[4];
                af[mi][3] = ap[8 * LDA + 4];
            }
#pragma unroll
            for (int ni = 0; ni < 4; ni++) {
                const uint32_t* bp = &Bb[(ks * 8 + lc) * LDB + wn * 32 + ni * 8 + lr];
                bf[ni][0] = bp[0];
                bf[ni][1] = bp[4 * LDB];
            }
#pragma unroll
            for (int mi = 0; mi < 4; mi++)
#pragma unroll
                for (int ni = 0; ni < 4; ni++)
                    mma_tf32(acc[mi][ni], af[mi], bf[ni]);
        }
        __syncthreads();
    }

#pragma unroll
    for (int mi = 0; mi < 4; mi++) {
        const int r0 = by * BM + wm * 64 + mi * 16 + lr;
#pragma unroll
        for (int ni = 0; ni < 4; ni++) {
            const int c0 = bx * BN + wn * 32 + ni * 8 + 2 * lc;
            *(float2*)&C[(size_t)r0 * N + c0]       = make_float2(acc[mi][ni][0], acc[mi][ni][1]);
            *(float2*)&C[(size_t)(r0 + 8) * N + c0] = make_float2(acc[mi][ni][2], acc[mi][ni][3]);
        }
    }
#undef LOAD_TILE
}

// ---------------------------------------------------------------------------
// Tensor-core sliding-window attention. Block = (64-query tile, head),
// 4 warps; warp w owns query rows 16w..16w+15. QK^T and PV via tf32 mma.
// Epilogue writes tf32-rounded ctx (feeds out-proj without cvt).
// ---------------------------------------------------------------------------
__global__ __launch_bounds__(128) void attn_tc(const float* __restrict__ qkv,
                                               float* __restrict__ ctx) {
    extern __shared__ float sm[];
    float* Qs = sm;                    // [64][LQ]
    float* Ks = sm + 64 * LQ;          // [64][LQ]
    float* Ps = sm + 2 * 64 * LQ;      // [64][LQ]
    float* Vs = sm + 3 * 64 * LQ;      // [64][LV]

    const int qb = blockIdx.x;
    const int h  = blockIdx.y;
    const int t  = threadIdx.x;
    const int w  = t >> 5;
    const int lane = t & 31;
    const int lr = lane >> 2;
    const int lc = lane & 3;
    const int q0 = qb * 64;
    const int col0 = h * HD;

    // fill Q (rounded to tf32)
#pragma unroll
    for (int i = 0; i < 8; i++) {
        int id = t + 128 * i;
        int r = id >> 4, c4 = (id & 15) << 2;
        float4 v = *(const float4*)&qkv[(size_t)(q0 + r) * QKV_N + col0 + c4];
        v.x = __uint_as_float(f2tf(v.x));
        v.y = __uint_as_float(f2tf(v.y));
        v.z = __uint_as_float(f2tf(v.z));
        v.w = __uint_as_float(f2tf(v.w));
        *(float4*)&Qs[r * LQ + c4] = v;
    }

    float o[8][4];
#pragma unroll
    for (int nt = 0; nt < 8; nt++)
#pragma unroll
        for (int c = 0; c < 4; c++) o[nt][c] = 0.0f;
    float m[2] = {-1e30f, -1e30f};
    float l[2] = {0.0f, 0.0f};

    const int ktlo = (qb >= 4) ? qb - 4 : 0;
    for (int kt = ktlo; kt <= qb; kt++) {
        const int k0 = kt * 64;
        __syncthreads();
#pragma unroll
        for (int i = 0; i < 8; i++) {
            int id = t + 128 * i;
            int r = id >> 4, c4 = (id & 15) << 2;
            float4 kv = *(const float4*)&qkv[(size_t)(k0 + r) * QKV_N + EMB + col0 + c4];
            kv.x = __uint_as_float(f2tf(kv.x));
            kv.y = __uint_as_float(f2tf(kv.y));
            kv.z = __uint_as_float(f2tf(kv.z));
            kv.w = __uint_as_float(f2tf(kv.w));
            *(float4*)&Ks[r * LQ + c4] = kv;
            float4 vv = *(const float4*)&qkv[(size_t)(k0 + r) * QKV_N + 2 * EMB + col0 + c4];
            vv.x = __uint_as_float(f2tf(vv.x));
            vv.y = __uint_as_float(f2tf(vv.y));
            vv.z = __uint_as_float(f2tf(vv.z));
            vv.w = __uint_as_float(f2tf(vv.w));
            *(float4*)&Vs[r * LV + c4] = vv;
        }
        __syncthreads();

        // S = Q K^T   (warp's 16 rows x 64 keys)
        float acc[8][4];
#pragma unroll
        for (int nt = 0; nt < 8; nt++)
#pragma unroll
            for (int c = 0; c < 4; c++) acc[nt][c] = 0.0f;

        const uint32_t* Qu = (const uint32_t*)Qs;
        const uint32_t* Ku = (const uint32_t*)Ks;
#pragma unroll
        for (int ks = 0; ks < 8; ks++) {
            uint32_t af[4];
            const uint32_t* ap = &Qu[(16 * w + lr) * LQ + 8 * ks + lc];
            af[0] = ap[0];
            af[1] = ap[8 * LQ];
            af[2] = ap[4];
            af[3] = ap[8 * LQ + 4];
#pragma unroll
            for (int nt = 0; nt < 8; nt++) {
                uint32_t bf[2];
                const uint32_t* bp = &Ku[(8 * nt + lr) * LQ + 8 * ks + lc];
                bf[0] = bp[0];
                bf[1] = bp[4];
                mma_tf32(acc[nt], af, bf);
            }
        }

        // masked online softmax: 2 rows per thread (lr, lr+8 within warp tile)
#pragma unroll
        for (int i = 0; i < 2; i++) {
            const int qi = q0 + 16 * w + lr + 8 * i;
            float sv[16];
            float mt = -1e30f;
#pragma unroll
            for (int nt = 0; nt < 8; nt++) {
#pragma unroll
                for (int c = 0; c < 2; c++) {
                    int kj = k0 + 8 * nt + 2 * lc + c;
                    bool ok = (kj <= qi) && (kj > qi - WIN);
                    float s = acc[nt][2 * i + c] * 0.125f;
                    sv[nt * 2 + c] = ok ? s : -1e30f;
                    mt = fmaxf(mt, sv[nt * 2 + c]);
                }
            }
            mt = fmaxf(mt, __shfl_xor_sync(0xffffffffu, mt, 1));
            mt = fmaxf(mt, __shfl_xor_sync(0xffffffffu, mt, 2));

            float alpha = 1.0f;
            if (mt > m[i]) { alpha = __expf(m[i] - mt); m[i] = mt; }

            float ls = 0.0f;
            float p[16];
#pragma unroll
            for (int j = 0; j < 16; j++) {
                p[j] = (sv[j] > -1e29f) ? __expf(sv[j] - m[i]) : 0.0f;
                ls += p[j];
            }
            ls += __shfl_xor_sync(0xffffffffu, ls, 1);
            ls += __shfl_xor_sync(0xffffffffu, ls, 2);

            l[i] = l[i] * alpha + ls;
#pragma unroll
            for (int nt = 0; nt < 8; nt++) {
                o[nt][2 * i]     *= alpha;
                o[nt][2 * i + 1] *= alpha;
                float2 pr = make_float2(__uint_as_float(f2tf(p[nt * 2])),
                                        __uint_as_float(f2tf(p[nt * 2 + 1])));
                *(float2*)&Ps[(16 * w + lr + 8 * i) * LQ + 8 * nt + 2 * lc] = pr;
            }
        }
        __syncwarp();

        // O += P V
        const uint32_t* Pu = (const uint32_t*)Ps;
        const uint32_t* Vu = (const uint32_t*)Vs;
#pragma unroll
        for (int ks = 0; ks < 8; ks++) {
            uint32_t pa[4];
            const uint32_t* pp = &Pu[(16 * w + lr) * LQ + 8 * ks + lc];
            pa[0] = pp[0];
            pa[1] = pp[8 * LQ];
            pa[2] = pp[4];
            pa[3] = pp[8 * LQ + 4];
#pragma unroll
            for (int nt = 0; nt < 8; nt++) {
                uint32_t vb[2];
                const uint32_t* vp = &Vu[(8 * ks + lc) * LV + 8 * nt + lr];
                vb[0] = vp[0];
                vb[1] = vp[4 * LV];
                mma_tf32(o[nt], pa, vb);
            }
        }
    }

    // epilogue: normalize, round to tf32, store
    const float inv0 = 1.0f / l[0];
    const float inv1 = 1.0f / l[1];
    const int row0 = q0 + 16 * w + lr;
#pragma unroll
    for (int nt = 0; nt < 8; nt++) {
        int c0 = col0 + 8 * nt + 2 * lc;
        *(float2*)&ctx[(size_t)row0 * EMB + c0] =
            make_float2(__uint_as_float(f2tf(o[nt][0] * inv0)),
                        __uint_as_float(f2tf(o[nt][1] * inv0)));
        *(float2*)&ctx[(size_t)(row0 + 8) * EMB + c0] =
            make_float2(__uint_as_float(f2tf(o[nt][2] * inv1)),
                        __uint_as_float(f2tf(o[nt][3] * inv1)));
    }
}

// ---------------------------------------------------------------------------
extern "C" void kernel_launch(void* const* d_in, const int* in_sizes, int n_in,
                              void* d_out, int out_size) {
    const float* x     = (const float*)d_in[0];
    const float* w_qkv = (const float*)d_in[2];
    const float* w_out = (const float*)d_in[3];
    float* out = (float*)d_out;

    float *qkv, *ctx, *xr, *wqkvr, *woutr;
    cudaGetSymbolAddress((void**)&qkv, g_qkv);
    cudaGetSymbolAddress((void**)&ctx, g_attn);
    cudaGetSymbolAddress((void**)&xr, g_xr);
    cudaGetSymbolAddress((void**)&wqkvr, g_wqkvr);
    cudaGetSymbolAddress((void**)&woutr, g_woutr);

    static bool attrs_set = false;
    if (!attrs_set) {
        cudaFuncSetAttribute(attn_tc, cudaFuncAttributeMaxDynamicSharedMemorySize, ATTN_SMEM);
        cudaFuncSetAttribute(tf32gemm, cudaFuncAttributeMaxDynamicSharedMemorySize, GEMM_SMEM);
        attrs_set = true;
    }

    // 0) pre-round GEMM operands to tf32
    round_tf32<<<(SEQ * EMB / 4 + 255) / 256, 256>>>((const float4*)x, (float4*)xr, SEQ * EMB / 4);
    round_tf32<<<(EMB * QKV_N / 4 + 255) / 256, 256>>>((const float4*)w_qkv, (float4*)wqkvr, EMB * QKV_N / 4);
    round_tf32<<<(EMB * EMB / 4 + 255) / 256, 256>>>((const float4*)w_out, (float4*)woutr, EMB * EMB / 4);

    // 1) qkv = x @ w_qkv
    tf32gemm<<<dim3(QKV_N / BN, SEQ / BM), 256, GEMM_SMEM>>>(xr, wqkvr, qkv, SEQ, QKV_N, EMB);
    // 2) attention
    attn_tc<<<dim3(SEQ / 64, NH), 128, ATTN_SMEM>>>(qkv, ctx);
    // 3) out = ctx @ w_out
    tf32gemm<<<dim3(EMB / BN, SEQ / BM), 256, GEMM_SMEM>>>(ctx, woutr, out, SEQ, EMB, EMB);
}